// round 15
// baseline (speedup 1.0000x reference)
#include <cuda_runtime.h>
#include <stdint.h>

// ---------------- problem constants ----------------
#define MAXM      300000
#define NCLS      80
#define TOPK      1000
#define CONF      0.001f
#define NMSTH     0.5f
#define CLSOFF    4096.0f
#define CAND_CAP  4096
#define NBINS     4096
#define NLCAP     384      // contested rows staged in smem
#define CLN       8        // cluster size for the fused tail kernel

// ---------------- device scratch (zero-initialized at load) ----------------
// All reset to zero at the END of k_tail (phase 3) for the next replay.
__device__ uint32_t g_scorebits[MAXM];
__device__ uint32_t g_hist1[NBINS];
__device__ uint32_t g_hist2[NBINS];
__device__ uint32_t g_prefix1;        // benign identical-value race (hist2 blocks)
__device__ uint32_t g_need;           // benign identical-value race (hist2 blocks)
__device__ uint32_t g_cand_cnt;
__device__ unsigned long long g_cand[CAND_CAP];
// ranked top-k data (fully overwritten each replay)
__device__ float   g_x1[TOPK], g_y1[TOPK], g_x2[TOPK], g_y2[TOPK];
__device__ float   g_area[TOPK], g_scr[TOPK];
__device__ float4  g_box[TOPK];
__device__ int     g_lab[TOPK];
__device__ uint32_t g_sup[TOPK * 32];  // fully overwritten each replay
__device__ uint32_t g_rowNZ[32];
__device__ uint32_t g_keep0[32];

__device__ __forceinline__ float sigf(float x) {
    return 1.0f / (1.0f + expf(-x));
}

// Two-level suffix scan (1024 threads): returns count strictly ABOVE this
// thread's chunk. warpTot = 32-entry smem array. Exactly 2 barriers.
__device__ __forceinline__ uint32_t suffix_above(uint32_t csum,
                                                 uint32_t* warpTot) {
    int lane = threadIdx.x & 31, warp = threadIdx.x >> 5;
    uint32_t S = csum;
#pragma unroll
    for (int off = 1; off < 32; off <<= 1) {
        uint32_t v = __shfl_down_sync(0xFFFFFFFFu, S, off);
        if (lane + off < 32) S += v;
    }
    if (lane == 0) warpTot[warp] = S;
    __syncthreads();
    if (threadIdx.x < 32) {
        uint32_t T = warpTot[threadIdx.x];
        uint32_t W = T;
#pragma unroll
        for (int off = 1; off < 32; off <<= 1) {
            uint32_t v = __shfl_down_sync(0xFFFFFFFFu, W, off);
            if (threadIdx.x + off < 32) W += v;
        }
        warpTot[threadIdx.x] = W - T;
    }
    __syncthreads();
    return warpTot[warp] + (S - csum);
}

// ============================================================================
// K1: coalesced max-logit (4 lanes/anchor, 5 even float4 loads/lane)
// ============================================================================
__global__ void __launch_bounds__(512) k_score(const float* __restrict__ obj,
                                               const float* __restrict__ cls,
                                               int M) {
    __shared__ uint32_t sh[NBINS];
    for (int i = threadIdx.x; i < NBINS; i += 512) sh[i] = 0;
    __syncthreads();

    int warp = threadIdx.x >> 5, lane = threadIdx.x & 31;
    int g = lane >> 2, s = lane & 3;
    int base = blockIdx.x * 512 + warp * 32;
    const float4* c4 = (const float4*)cls;

#pragma unroll
    for (int it = 0; it < 4; it++) {
        int m = base + it * 8 + g;
        float v = -1e30f;
        if (m < M) {
            const float4* row = c4 + (size_t)m * 20;
            float4 a0 = row[s];
            float4 a1 = row[s + 4];
            float4 a2 = row[s + 8];
            float4 a3 = row[s + 12];
            float4 a4 = row[s + 16];
            float v0 = fmaxf(fmaxf(a0.x, a0.y), fmaxf(a0.z, a0.w));
            float v1 = fmaxf(fmaxf(a1.x, a1.y), fmaxf(a1.z, a1.w));
            float v2 = fmaxf(fmaxf(a2.x, a2.y), fmaxf(a2.z, a2.w));
            float v3 = fmaxf(fmaxf(a3.x, a3.y), fmaxf(a3.z, a3.w));
            float v4 = fmaxf(fmaxf(a4.x, a4.y), fmaxf(a4.z, a4.w));
            v = fmaxf(fmaxf(v0, v1), fmaxf(fmaxf(v2, v3), v4));
        }
        v = fmaxf(v, __shfl_down_sync(0xFFFFFFFFu, v, 2, 4));
        v = fmaxf(v, __shfl_down_sync(0xFFFFFFFFu, v, 1, 4));
        if (s == 0 && m < M) {
            // monotone: max_c sqrt(sig(o)*sig(c)) == sqrt(sig(o)*sig(max_c))
            float f = sqrtf(sigf(obj[m]) * sigf(v));
            uint32_t bits = __float_as_uint(f);
            g_scorebits[m] = bits;
            atomicAdd(&sh[bits >> 20], 1u);
        }
    }
    __syncthreads();
    for (int i = threadIdx.x; i < NBINS; i += 512) {
        uint32_t v = sh[i];
        if (v) atomicAdd(&g_hist1[i], v);
    }
}

// ============================================================================
// K2: INLINE redundant round-1 select (every block) + refinement hist
// ============================================================================
__global__ void __launch_bounds__(1024) k_hist2(int M) {
    __shared__ uint32_t sh[NBINS];
    __shared__ uint32_t warpTot[32];
    __shared__ uint32_t spre;
    int t = threadIdx.x;

    uint4 a = __ldcg(&((const uint4*)g_hist1)[t]);
    uint32_t hh[4] = {a.x, a.y, a.z, a.w};
    uint32_t csum = hh[0] + hh[1] + hh[2] + hh[3];
    uint32_t cum = suffix_above(csum, warpTot);
#pragma unroll
    for (int c = 3; c >= 0; c--) {
        uint32_t bc = hh[c];
        if (bc > 0 && cum < (uint32_t)TOPK && cum + bc >= (uint32_t)TOPK) {
            uint32_t pre = (uint32_t)(t * 4 + c) << 20;
            spre = pre;
            g_prefix1 = pre;              // identical across blocks: benign race
            g_need = (uint32_t)TOPK - cum;
        }
        cum += bc;
    }
    sh[t] = 0; sh[t + 1024] = 0; sh[t + 2048] = 0; sh[t + 3072] = 0;
    __syncthreads();
    uint32_t pre = spre;

    const uint4* sb4 = (const uint4*)g_scorebits;
    int n4 = M >> 2;
    for (int i = blockIdx.x * 1024 + t; i < n4; i += gridDim.x * 1024) {
        uint4 v = sb4[i];
        if ((v.x & 0xFFF00000u) == pre) atomicAdd(&sh[(v.x >> 8) & 0xFFFu], 1u);
        if ((v.y & 0xFFF00000u) == pre) atomicAdd(&sh[(v.y >> 8) & 0xFFFu], 1u);
        if ((v.z & 0xFFF00000u) == pre) atomicAdd(&sh[(v.z >> 8) & 0xFFFu], 1u);
        if ((v.w & 0xFFF00000u) == pre) atomicAdd(&sh[(v.w >> 8) & 0xFFFu], 1u);
    }
    if (blockIdx.x == 0 && t < (M & 3)) {
        uint32_t b = g_scorebits[(n4 << 2) + t];
        if ((b & 0xFFF00000u) == pre) atomicAdd(&sh[(b >> 8) & 0xFFFu], 1u);
    }
    __syncthreads();
    for (int i = t; i < NBINS; i += 1024) {
        uint32_t v = sh[i];
        if (v) atomicAdd(&g_hist2[i], v);
    }
}

// ============================================================================
// K3: INLINE redundant round-2 select (every block) + gather
// ============================================================================
__global__ void __launch_bounds__(1024) k_gather(int M) {
    __shared__ uint32_t warpTot[32];
    __shared__ uint32_t sT;
    int t = threadIdx.x;

    uint32_t need = g_need;
    uint32_t pre1 = g_prefix1;
    uint4 a = __ldcg(&((const uint4*)g_hist2)[t]);
    uint32_t hh[4] = {a.x, a.y, a.z, a.w};
    uint32_t csum = hh[0] + hh[1] + hh[2] + hh[3];
    uint32_t cum = suffix_above(csum, warpTot);
#pragma unroll
    for (int c = 3; c >= 0; c--) {
        uint32_t bc = hh[c];
        if (bc > 0 && cum < need && cum + bc >= need)
            sT = pre1 | ((uint32_t)(t * 4 + c) << 8);
        cum += bc;
    }
    __syncthreads();
    uint32_t T = sT;

    const uint4* sb4 = (const uint4*)g_scorebits;
    int n4 = M >> 2;
    for (int i = blockIdx.x * 1024 + t; i < n4; i += gridDim.x * 1024) {
        uint4 v = sb4[i];
        uint32_t m0 = (uint32_t)(i << 2);
        uint32_t bb[4] = {v.x, v.y, v.z, v.w};
#pragma unroll
        for (int c = 0; c < 4; c++) {
            if (bb[c] >= T) {
                uint32_t p = atomicAdd(&g_cand_cnt, 1u);
                if (p < CAND_CAP)
                    g_cand[p] = ((unsigned long long)bb[c] << 32) |
                                (unsigned long long)(0xFFFFFFFFu - (m0 + c));
            }
        }
    }
    if (blockIdx.x == 0 && t < (M & 3)) {
        uint32_t m = (uint32_t)((n4 << 2) + t);
        uint32_t b = g_scorebits[m];
        if (b >= T) {
            uint32_t p = atomicAdd(&g_cand_cnt, 1u);
            if (p < CAND_CAP)
                g_cand[p] = ((unsigned long long)b << 32) |
                            (unsigned long long)(0xFFFFFFFFu - m);
        }
    }
}

// ============================================================================
// K4 (fused tail, 8-CTA cluster): rank -> cluster.sync -> sup -> cluster.sync
//     -> block0: sparse NMS sweep + output + state reset
// ============================================================================
__global__ void __launch_bounds__(1024, 1) __cluster_dims__(CLN, 1, 1)
k_tail(const float* __restrict__ cls, const float4* __restrict__ boxp,
       float* __restrict__ out, int out_size) {
    extern __shared__ char dsm[];
    __shared__ uint32_t keep[32];
    __shared__ uint32_t rnz[32];
    __shared__ int nlist;

    int t = threadIdx.x;
    int warp = t >> 5, lane = t & 31;
    int blk = blockIdx.x;   // 0..7 within the single cluster

    // ---------------- phase 1: rank (warp handles 4 interleaved candidates) ----
    {
        unsigned long long* keys = (unsigned long long*)dsm;   // 32 KB
        uint32_t n = g_cand_cnt;
        if (n > CAND_CAP) n = CAND_CAP;
        for (uint32_t i = t; i < n; i += 1024) keys[i] = __ldcg(&g_cand[i]);
        __syncthreads();

        uint32_t cbase = (uint32_t)(blk * 32 + warp);   // 0..255
        unsigned long long kq[4];
        int rq[4] = {0, 0, 0, 0};
        bool aq[4];
#pragma unroll
        for (int q = 0; q < 4; q++) {
            uint32_t c = cbase + (uint32_t)q * 256u;
            aq[q] = (c < n);
            kq[q] = aq[q] ? keys[c] : 0xFFFFFFFFFFFFFFFFull;
        }
        for (uint32_t j0 = 0; j0 < n; j0 += 32) {
            uint32_t j = j0 + lane;
            bool in = (j < n);
            unsigned long long kj = in ? keys[j] : 0ull;
#pragma unroll
            for (int q = 0; q < 4; q++)
                rq[q] += __popc(__ballot_sync(0xFFFFFFFFu, in && kj > kq[q]));
        }
#pragma unroll
        for (int q = 0; q < 4; q++) {
            if (!aq[q]) continue;
            int r = rq[q];
            if (r >= TOPK) continue;
            unsigned long long k = kq[q];
            uint32_t idx = 0xFFFFFFFFu - (uint32_t)(k & 0xFFFFFFFFull);
            // warp-parallel first-max argmax over 80 classes
            float best = -1e30f;
            int lab = 0x7FFFFFFF;
            if (lane < 20) {
                float4 v = __ldg(&((const float4*)(cls + (size_t)idx * NCLS))[lane]);
                best = v.x; lab = lane * 4;
                if (v.y > best) { best = v.y; lab = lane * 4 + 1; }
                if (v.z > best) { best = v.z; lab = lane * 4 + 2; }
                if (v.w > best) { best = v.w; lab = lane * 4 + 3; }
            }
#pragma unroll
            for (int off = 16; off > 0; off >>= 1) {
                float ob = __shfl_down_sync(0xFFFFFFFFu, best, off);
                int   ol = __shfl_down_sync(0xFFFFFFFFu, lab, off);
                if (ob > best || (ob == best && ol < lab)) { best = ob; lab = ol; }
            }
            lab = __shfl_sync(0xFFFFFFFFu, lab, 0);
            if (lane == 0) {
                float scr = __uint_as_float((uint32_t)(k >> 32));
                float4 b = __ldg(&boxp[idx]);
                float off = (float)lab * CLSOFF;
                float x1 = b.x + off, y1 = b.y + off;
                float x2 = b.z + off, y2 = b.w + off;
                g_box[r] = b;
                g_scr[r] = scr;
                g_lab[r] = lab;
                g_x1[r] = x1; g_y1[r] = y1; g_x2[r] = x2; g_y2[r] = y2;
                g_area[r] = fmaxf(x2 - x1, 0.0f) * fmaxf(y2 - y1, 0.0f);
                if (scr > CONF) atomicOr(&g_keep0[r >> 5], 1u << (r & 31));
            }
        }
    }
    asm volatile("barrier.cluster.arrive.aligned;" ::: "memory");
    asm volatile("barrier.cluster.wait.aligned;" ::: "memory");

    // ---------------- phase 2: suppression matrix (4 row-bands per block) ----
    {
        float* sx1   = (float*)dsm;          // reuse buffer: 24 KB total
        float* sy1   = sx1 + TOPK;
        float* sx2   = sy1 + TOPK;
        float* sy2   = sx2 + TOPK;
        float* sarea = sy2 + TOPK;
        int*   slab  = (int*)(sarea + TOPK);
        for (int i = t; i < TOPK; i += 1024) {
            sx1[i] = __ldcg(&g_x1[i]); sy1[i] = __ldcg(&g_y1[i]);
            sx2[i] = __ldcg(&g_x2[i]); sy2[i] = __ldcg(&g_y2[i]);
            sarea[i] = __ldcg(&g_area[i]); slab[i] = __ldcg(&g_lab[i]);
        }
        __syncthreads();

        int w = warp;            // j-word
        int jbase = w * 32;
#pragma unroll
        for (int q = 0; q < 4; q++) {
            int i = (blk * 4 + q) * 32 + lane;
            uint32_t bits = 0;
            if (i < TOPK && jbase < i) {
                int lb = slab[i];
                float ix1 = sx1[i], iy1 = sy1[i], ix2 = sx2[i], iy2 = sy2[i];
                float ia = sarea[i];
                int jend = jbase + 32; if (jend > i) jend = i;
                for (int j = jbase; j < jend; j++) {
                    if (slab[j] == lb) {   // cross-class IoU is exactly 0
                        float xx1 = fmaxf(ix1, sx1[j]);
                        float yy1 = fmaxf(iy1, sy1[j]);
                        float xx2 = fminf(ix2, sx2[j]);
                        float yy2 = fminf(iy2, sy2[j]);
                        float inter = fmaxf(xx2 - xx1, 0.0f) * fmaxf(yy2 - yy1, 0.0f);
                        float iou = inter / (ia + sarea[j] - inter + 1e-9f);
                        if (iou > NMSTH) bits |= (1u << (j - jbase));
                    }
                }
            }
            if (i < TOPK) {
                g_sup[i * 32 + w] = bits;
                if (bits) atomicOr(&g_rowNZ[i >> 5], 1u << (i & 31));
            }
        }
    }
    asm volatile("barrier.cluster.arrive.aligned;" ::: "memory");
    asm volatile("barrier.cluster.wait.aligned;" ::: "memory");

    // ---------------- phase 3: block 0 — sparse sweep + output + reset ----
    if (blk != 0) return;
    {
        uint32_t* srow = (uint32_t*)dsm;               // NLCAP*32 u32 = 48 KB
        int* list = (int*)(srow + NLCAP * 32);         // 4 KB

        if (t < 32) { keep[t] = __ldcg(&g_keep0[t]); rnz[t] = __ldcg(&g_rowNZ[t]); }
        __syncthreads();

        if (t < 32) {
            int cnt = 0;
            for (int w2 = 0; w2 < 32; w2++) {
                uint32_t rb = rnz[w2];
                int bit = (rb >> lane) & 1;
                uint32_t bal = __ballot_sync(0xFFFFFFFFu, bit);
                if (bit) {
                    int pos = cnt + __popc(bal & ((1u << lane) - 1u));
                    list[pos] = w2 * 32 + lane;
                }
                cnt += __popc(bal);
            }
            if (lane == 0) nlist = cnt;
        }
        __syncthreads();

        int nl = nlist;
        for (int l = warp; l < nl && l < NLCAP; l += 32)
            srow[l * 32 + lane] = __ldcg(&g_sup[list[l] * 32 + lane]);
        __syncthreads();

        if (t < 32) {
            uint32_t kw = keep[lane];
            for (int l = 0; l < nl; l++) {
                int i = list[l];
                int iw = i >> 5;
                uint32_t ib = (uint32_t)(i & 31);
                uint32_t ltm = (lane < iw) ? 0xFFFFFFFFu
                             : ((lane == iw) ? ((1u << ib) - 1u) : 0u);
                uint32_t row = (l < NLCAP) ? srow[l * 32 + lane]
                                           : __ldcg(&g_sup[i * 32 + lane]);
                uint32_t v = row & kw & ltm;
                if (__any_sync(0xFFFFFFFFu, v != 0u)) {
                    if (lane == iw) kw &= ~(1u << ib);
                }
            }
            keep[lane] = kw;
        }
        __syncthreads();

        if (t < TOPK) {
            float kf = ((keep[t >> 5] >> (t & 31)) & 1u) ? 1.0f : 0.0f;
            float4 b = __ldcg(&g_box[t]);   // raw (un-offset) box
            out[t * 5 + 0] = __ldcg(&g_scr[t]) * kf;
            out[t * 5 + 1] = b.x * kf;
            out[t * 5 + 2] = b.y * kf;
            out[t * 5 + 3] = b.z * kf;
            out[t * 5 + 4] = b.w * kf;
            if (out_size >= 6000) out[5000 + t] = (float)__ldcg(&g_lab[t]);
            if (out_size >= 7000) out[6000 + t] = kf;
        }

        // ---- reset all scratch state for the next replay ----
        for (int i = t; i < NBINS; i += 1024) { g_hist1[i] = 0; g_hist2[i] = 0; }
        if (t < 32) { g_rowNZ[t] = 0; g_keep0[t] = 0; }
        if (t == 0) g_cand_cnt = 0;
    }
}

// ---------------- launch (4 kernels) ----------------
extern "C" void kernel_launch(void* const* d_in, const int* in_sizes, int n_in,
                              void* d_out, int out_size) {
    const float* obj   = (const float*)d_in[0];
    const float* cls   = (const float*)d_in[1];
    const float4* boxp = (const float4*)d_in[2];
    float* out = (float*)d_out;
    int M = in_sizes[0];
    if (M > MAXM) M = MAXM;
    (void)n_in;

    const int TAIL_SMEM = 56 * 1024;   // max(keys 32K, boxes 24K, srow+list 52K)
    cudaFuncSetAttribute(k_tail, cudaFuncAttributeMaxDynamicSharedMemorySize,
                         TAIL_SMEM);

    int gsc = (M + 511) / 512;
    int n4 = M >> 2;
    int gb = (n4 + 1023) / 1024;
    if (gb > 148) gb = 148;
    if (gb < 1) gb = 1;

    k_score<<<gsc, 512>>>(obj, cls, M);
    k_hist2<<<gb, 1024>>>(M);
    k_gather<<<gb, 1024>>>(M);
    k_tail<<<CLN, 1024, TAIL_SMEM>>>(cls, boxp, out, out_size);
}

// round 16
// speedup vs baseline: 1.2807x; 1.2807x over previous
#include <cuda_runtime.h>
#include <stdint.h>

// ---------------- problem constants ----------------
#define MAXM      300000
#define NCLS      80
#define TOPK      1000
#define CONF      0.001f
#define NMSTH     0.5f
#define CLSOFF    4096.0f
#define CAND_CAP  4096
#define NBINS     4096
#define NLCAP     384      // contested rows staged in static smem

// ---------------- device scratch (zero-initialized at load) ----------------
// All reset to zero at the END of k_nms for the next replay.
__device__ uint32_t g_scorebits[MAXM];
__device__ uint32_t g_hist1[NBINS];
__device__ uint32_t g_hist2[NBINS];
__device__ uint32_t g_prefix1;        // benign identical-value race (hist2 blocks)
__device__ uint32_t g_need;           // benign identical-value race (hist2 blocks)
__device__ uint32_t g_cand_cnt;
__device__ unsigned long long g_cand[CAND_CAP];
// ranked top-k data (fully overwritten each replay)
__device__ float   g_x1[TOPK], g_y1[TOPK], g_x2[TOPK], g_y2[TOPK];
__device__ float   g_area[TOPK], g_scr[TOPK];
__device__ float4  g_box[TOPK];
__device__ int     g_lab[TOPK];
__device__ uint32_t g_sup[TOPK * 32];  // fully overwritten each replay
__device__ uint32_t g_rowNZ[32];
__device__ uint32_t g_keep0[32];

__device__ __forceinline__ float sigf(float x) {
    return 1.0f / (1.0f + expf(-x));
}

// Two-level suffix scan (1024 threads): returns count strictly ABOVE this
// thread's chunk. warpTot = 32-entry smem array. Exactly 2 barriers.
__device__ __forceinline__ uint32_t suffix_above(uint32_t csum,
                                                 uint32_t* warpTot) {
    int lane = threadIdx.x & 31, warp = threadIdx.x >> 5;
    uint32_t S = csum;
#pragma unroll
    for (int off = 1; off < 32; off <<= 1) {
        uint32_t v = __shfl_down_sync(0xFFFFFFFFu, S, off);
        if (lane + off < 32) S += v;
    }
    if (lane == 0) warpTot[warp] = S;
    __syncthreads();
    if (threadIdx.x < 32) {
        uint32_t T = warpTot[threadIdx.x];
        uint32_t W = T;
#pragma unroll
        for (int off = 1; off < 32; off <<= 1) {
            uint32_t v = __shfl_down_sync(0xFFFFFFFFu, W, off);
            if (threadIdx.x + off < 32) W += v;
        }
        warpTot[threadIdx.x] = W - T;
    }
    __syncthreads();
    return warpTot[warp] + (S - csum);
}

// ============================================================================
// K1: coalesced max-logit (2 lanes/anchor, 10 even float4 loads/lane -> 2x MLP)
//     512 threads, 512 anchors per block; fused score + 12-bit hist
// ============================================================================
__global__ void __launch_bounds__(512) k_score(const float* __restrict__ obj,
                                               const float* __restrict__ cls,
                                               int M) {
    __shared__ uint32_t sh[NBINS];
    for (int i = threadIdx.x; i < NBINS; i += 512) sh[i] = 0;
    __syncthreads();

    int warp = threadIdx.x >> 5, lane = threadIdx.x & 31;
    int g = lane >> 1, s = lane & 1;            // 16 anchors/warp/iter, 2 lanes each
    int base = blockIdx.x * 512 + warp * 32;    // 16 warps x 32 anchors

    const float4* c4 = (const float4*)cls;
#pragma unroll
    for (int it = 0; it < 2; it++) {
        int m = base + it * 16 + g;
        float v = -1e30f;
        if (m < M) {
            const float4* row = c4 + (size_t)m * 20;
            float4 a0 = row[s];                 // 10 independent coalesced LDG.128
            float4 a1 = row[s + 2];
            float4 a2 = row[s + 4];
            float4 a3 = row[s + 6];
            float4 a4 = row[s + 8];
            float4 a5 = row[s + 10];
            float4 a6 = row[s + 12];
            float4 a7 = row[s + 14];
            float4 a8 = row[s + 16];
            float4 a9 = row[s + 18];
            float v0 = fmaxf(fmaxf(a0.x, a0.y), fmaxf(a0.z, a0.w));
            float v1 = fmaxf(fmaxf(a1.x, a1.y), fmaxf(a1.z, a1.w));
            float v2 = fmaxf(fmaxf(a2.x, a2.y), fmaxf(a2.z, a2.w));
            float v3 = fmaxf(fmaxf(a3.x, a3.y), fmaxf(a3.z, a3.w));
            float v4 = fmaxf(fmaxf(a4.x, a4.y), fmaxf(a4.z, a4.w));
            float v5 = fmaxf(fmaxf(a5.x, a5.y), fmaxf(a5.z, a5.w));
            float v6 = fmaxf(fmaxf(a6.x, a6.y), fmaxf(a6.z, a6.w));
            float v7 = fmaxf(fmaxf(a7.x, a7.y), fmaxf(a7.z, a7.w));
            float v8 = fmaxf(fmaxf(a8.x, a8.y), fmaxf(a8.z, a8.w));
            float v9 = fmaxf(fmaxf(a9.x, a9.y), fmaxf(a9.z, a9.w));
            v0 = fmaxf(v0, v5); v1 = fmaxf(v1, v6); v2 = fmaxf(v2, v7);
            v3 = fmaxf(v3, v8); v4 = fmaxf(v4, v9);
            v = fmaxf(fmaxf(v0, v1), fmaxf(fmaxf(v2, v3), v4));
        }
        v = fmaxf(v, __shfl_down_sync(0xFFFFFFFFu, v, 1, 2));
        if (s == 0 && m < M) {
            // monotone: max_c sqrt(sig(o)*sig(c)) == sqrt(sig(o)*sig(max_c))
            float f = sqrtf(sigf(obj[m]) * sigf(v));
            uint32_t bits = __float_as_uint(f);
            g_scorebits[m] = bits;
            atomicAdd(&sh[bits >> 20], 1u);
        }
    }
    __syncthreads();
    for (int i = threadIdx.x; i < NBINS; i += 512) {
        uint32_t v = sh[i];
        if (v) atomicAdd(&g_hist1[i], v);
    }
}

// ============================================================================
// K2: INLINE redundant round-1 select (every block) + refinement hist
// ============================================================================
__global__ void __launch_bounds__(1024) k_hist2(int M) {
    __shared__ uint32_t sh[NBINS];
    __shared__ uint32_t warpTot[32];
    __shared__ uint32_t spre;
    int t = threadIdx.x;

    uint4 a = __ldcg(&((const uint4*)g_hist1)[t]);
    uint32_t hh[4] = {a.x, a.y, a.z, a.w};
    uint32_t csum = hh[0] + hh[1] + hh[2] + hh[3];
    uint32_t cum = suffix_above(csum, warpTot);
#pragma unroll
    for (int c = 3; c >= 0; c--) {
        uint32_t bc = hh[c];
        if (bc > 0 && cum < (uint32_t)TOPK && cum + bc >= (uint32_t)TOPK) {
            uint32_t pre = (uint32_t)(t * 4 + c) << 20;
            spre = pre;
            g_prefix1 = pre;              // identical across blocks: benign race
            g_need = (uint32_t)TOPK - cum;
        }
        cum += bc;
    }
    sh[t] = 0; sh[t + 1024] = 0; sh[t + 2048] = 0; sh[t + 3072] = 0;
    __syncthreads();
    uint32_t pre = spre;

    const uint4* sb4 = (const uint4*)g_scorebits;
    int n4 = M >> 2;
    for (int i = blockIdx.x * 1024 + t; i < n4; i += gridDim.x * 1024) {
        uint4 v = sb4[i];
        if ((v.x & 0xFFF00000u) == pre) atomicAdd(&sh[(v.x >> 8) & 0xFFFu], 1u);
        if ((v.y & 0xFFF00000u) == pre) atomicAdd(&sh[(v.y >> 8) & 0xFFFu], 1u);
        if ((v.z & 0xFFF00000u) == pre) atomicAdd(&sh[(v.z >> 8) & 0xFFFu], 1u);
        if ((v.w & 0xFFF00000u) == pre) atomicAdd(&sh[(v.w >> 8) & 0xFFFu], 1u);
    }
    if (blockIdx.x == 0 && t < (M & 3)) {
        uint32_t b = g_scorebits[(n4 << 2) + t];
        if ((b & 0xFFF00000u) == pre) atomicAdd(&sh[(b >> 8) & 0xFFFu], 1u);
    }
    __syncthreads();
    for (int i = t; i < NBINS; i += 1024) {
        uint32_t v = sh[i];
        if (v) atomicAdd(&g_hist2[i], v);
    }
}

// ============================================================================
// K3: INLINE redundant round-2 select (every block) + gather
// ============================================================================
__global__ void __launch_bounds__(1024) k_gather(int M) {
    __shared__ uint32_t warpTot[32];
    __shared__ uint32_t sT;
    int t = threadIdx.x;

    uint32_t need = g_need;
    uint32_t pre1 = g_prefix1;
    uint4 a = __ldcg(&((const uint4*)g_hist2)[t]);
    uint32_t hh[4] = {a.x, a.y, a.z, a.w};
    uint32_t csum = hh[0] + hh[1] + hh[2] + hh[3];
    uint32_t cum = suffix_above(csum, warpTot);
#pragma unroll
    for (int c = 3; c >= 0; c--) {
        uint32_t bc = hh[c];
        if (bc > 0 && cum < need && cum + bc >= need)
            sT = pre1 | ((uint32_t)(t * 4 + c) << 8);   // final 24-bit threshold
        cum += bc;
    }
    __syncthreads();
    uint32_t T = sT;

    const uint4* sb4 = (const uint4*)g_scorebits;
    int n4 = M >> 2;
    for (int i = blockIdx.x * 1024 + t; i < n4; i += gridDim.x * 1024) {
        uint4 v = sb4[i];
        uint32_t m0 = (uint32_t)(i << 2);
        uint32_t bb[4] = {v.x, v.y, v.z, v.w};
#pragma unroll
        for (int c = 0; c < 4; c++) {
            if (bb[c] >= T) {
                uint32_t p = atomicAdd(&g_cand_cnt, 1u);
                if (p < CAND_CAP)
                    g_cand[p] = ((unsigned long long)bb[c] << 32) |
                                (unsigned long long)(0xFFFFFFFFu - (m0 + c));
            }
        }
    }
    if (blockIdx.x == 0 && t < (M & 3)) {
        uint32_t m = (uint32_t)((n4 << 2) + t);
        uint32_t b = g_scorebits[m];
        if (b >= T) {
            uint32_t p = atomicAdd(&g_cand_cnt, 1u);
            if (p < CAND_CAP)
                g_cand[p] = ((unsigned long long)b << 32) |
                            (unsigned long long)(0xFFFFFFFFu - m);
        }
    }
}

// ============================================================================
// K4: warp-per-candidate rank (ballot count) + warp-parallel argmax + fetch
// ============================================================================
__global__ void __launch_bounds__(1024) k_rank(const float* __restrict__ cls,
                                               const float4* __restrict__ boxp) {
    __shared__ unsigned long long keys[CAND_CAP];
    int t = threadIdx.x;
    uint32_t n = g_cand_cnt;
    if (n > CAND_CAP) n = CAND_CAP;
    if ((uint32_t)(blockIdx.x * 32) >= n) return;   // block-uniform early exit

    for (uint32_t i = t; i < n; i += 1024) keys[i] = g_cand[i];
    __syncthreads();

    int warp = t >> 5, lane = t & 31;
    uint32_t c = blockIdx.x * 32 + warp;
    if (c >= n) return;                              // warp-uniform
    unsigned long long k = keys[c];

    int r = 0;
    for (uint32_t j0 = 0; j0 < n; j0 += 32) {
        uint32_t j = j0 + lane;
        bool p = (j < n) && (keys[j] > k);
        r += __popc(__ballot_sync(0xFFFFFFFFu, p));
    }
    if (r >= TOPK) return;

    uint32_t idx = 0xFFFFFFFFu - (uint32_t)(k & 0xFFFFFFFFull);

    // warp-parallel first-max argmax over 80 classes (20 lanes x 1 float4)
    float best = -1e30f;
    int lab = 0x7FFFFFFF;
    if (lane < 20) {
        float4 v = __ldg(&((const float4*)(cls + (size_t)idx * NCLS))[lane]);
        best = v.x; lab = lane * 4;
        if (v.y > best) { best = v.y; lab = lane * 4 + 1; }
        if (v.z > best) { best = v.z; lab = lane * 4 + 2; }
        if (v.w > best) { best = v.w; lab = lane * 4 + 3; }
    }
#pragma unroll
    for (int off = 16; off > 0; off >>= 1) {
        float ob = __shfl_down_sync(0xFFFFFFFFu, best, off);
        int   ol = __shfl_down_sync(0xFFFFFFFFu, lab, off);
        if (ob > best || (ob == best && ol < lab)) { best = ob; lab = ol; }
    }
    lab = __shfl_sync(0xFFFFFFFFu, lab, 0);          // first-max index

    if (lane == 0) {
        float scr = __uint_as_float((uint32_t)(k >> 32));
        float4 b = __ldg(&boxp[idx]);
        float off = (float)lab * CLSOFF;
        float x1 = b.x + off, y1 = b.y + off;
        float x2 = b.z + off, y2 = b.w + off;
        g_box[r] = b;
        g_scr[r] = scr;
        g_lab[r] = lab;
        g_x1[r] = x1; g_y1[r] = y1; g_x2[r] = x2; g_y2[r] = y2;
        g_area[r] = fmaxf(x2 - x1, 0.0f) * fmaxf(y2 - y1, 0.0f);
        if (scr > CONF) atomicOr(&g_keep0[r >> 5], 1u << (r & 31));
    }
}

// ============================================================================
// K5: suppression bit-matrix, grid-wide (32 blocks x 1024), boxes in smem
// ============================================================================
__global__ void k_sup() {
    __shared__ float sx1[TOPK], sy1[TOPK], sx2[TOPK], sy2[TOPK], sarea[TOPK];
    __shared__ int   slab[TOPK];
    int t = threadIdx.x;
    for (int i = t; i < TOPK; i += 1024) {
        sx1[i] = g_x1[i]; sy1[i] = g_y1[i];
        sx2[i] = g_x2[i]; sy2[i] = g_y2[i];
        sarea[i] = g_area[i]; slab[i] = g_lab[i];
    }
    __syncthreads();

    int w = t >> 5;          // j-word
    int lane = t & 31;       // row within this block's 32-row band
    int i = blockIdx.x * 32 + lane;
    int jbase = w * 32;
    uint32_t bits = 0;
    if (i < TOPK && jbase < i) {
        int lb = slab[i];
        float ix1 = sx1[i], iy1 = sy1[i], ix2 = sx2[i], iy2 = sy2[i];
        float ia = sarea[i];
        int jend = jbase + 32; if (jend > i) jend = i;
        for (int j = jbase; j < jend; j++) {
            if (slab[j] == lb) {   // cross-class IoU is exactly 0 (offset geometry)
                float xx1 = fmaxf(ix1, sx1[j]);
                float yy1 = fmaxf(iy1, sy1[j]);
                float xx2 = fminf(ix2, sx2[j]);
                float yy2 = fminf(iy2, sy2[j]);
                float inter = fmaxf(xx2 - xx1, 0.0f) * fmaxf(yy2 - yy1, 0.0f);
                float iou = inter / (ia + sarea[j] - inter + 1e-9f);
                if (iou > NMSTH) bits |= (1u << (j - jbase));
            }
        }
    }
    if (i < TOPK) {
        g_sup[i * 32 + w] = bits;
        if (bits) atomicOr(&g_rowNZ[i >> 5], 1u << (i & 31));
    }
}

// ============================================================================
// K6: sparse greedy sweep + output + state reset for next replay
// ============================================================================
__global__ void k_nms(float* __restrict__ out, int out_size) {
    __shared__ uint32_t srow[NLCAP * 32];   // 48 KB: staged contested rows
    __shared__ int      list[1024];
    __shared__ int      nlist;
    __shared__ uint32_t keep[32];
    __shared__ uint32_t rnz[32];

    int t = threadIdx.x;
    int lane = t & 31;
    if (t < 32) { keep[t] = g_keep0[t]; rnz[t] = g_rowNZ[t]; }
    __syncthreads();

    // warp 0: build ascending list of contested rows
    if (t < 32) {
        int cnt = 0;
        for (int w2 = 0; w2 < 32; w2++) {
            uint32_t rb = rnz[w2];
            int bit = (rb >> lane) & 1;
            uint32_t bal = __ballot_sync(0xFFFFFFFFu, bit);
            if (bit) {
                int pos = cnt + __popc(bal & ((1u << lane) - 1u));
                list[pos] = w2 * 32 + lane;
            }
            cnt += __popc(bal);
        }
        if (lane == 0) nlist = cnt;
    }
    __syncthreads();

    // stage contested rows (first NLCAP) into smem
    int nl = nlist;
    for (int l = t >> 5; l < nl && l < NLCAP; l += 32)
        srow[l * 32 + lane] = g_sup[list[l] * 32 + lane];
    __syncthreads();

    // warp 0: serial greedy sweep, lane owns keep-word lane
    if (t < 32) {
        uint32_t kw = keep[lane];
        for (int l = 0; l < nl; l++) {
            int i = list[l];
            int iw = i >> 5;
            uint32_t ib = (uint32_t)(i & 31);
            uint32_t ltm = (lane < iw) ? 0xFFFFFFFFu
                         : ((lane == iw) ? ((1u << ib) - 1u) : 0u);
            uint32_t row = (l < NLCAP) ? srow[l * 32 + lane]
                                       : g_sup[i * 32 + lane];
            uint32_t v = row & kw & ltm;
            if (__any_sync(0xFFFFFFFFu, v != 0u)) {
                if (lane == iw) kw &= ~(1u << ib);
            }
        }
        keep[lane] = kw;
    }
    __syncthreads();

    if (t < TOPK) {
        float kf = ((keep[t >> 5] >> (t & 31)) & 1u) ? 1.0f : 0.0f;
        float4 b = g_box[t];   // raw (un-offset) box, matches reference
        out[t * 5 + 0] = g_scr[t] * kf;
        out[t * 5 + 1] = b.x * kf;
        out[t * 5 + 2] = b.y * kf;
        out[t * 5 + 3] = b.z * kf;
        out[t * 5 + 4] = b.w * kf;
        if (out_size >= 6000) out[5000 + t] = (float)g_lab[t];
        if (out_size >= 7000) out[6000 + t] = kf;
    }

    // ---- reset all scratch state for the next replay ----
    for (int i = t; i < NBINS; i += 1024) { g_hist1[i] = 0; g_hist2[i] = 0; }
    if (t < 32) { g_rowNZ[t] = 0; g_keep0[t] = 0; }
    if (t == 0) g_cand_cnt = 0;
}

// ---------------- launch (6 kernels) ----------------
extern "C" void kernel_launch(void* const* d_in, const int* in_sizes, int n_in,
                              void* d_out, int out_size) {
    const float* obj   = (const float*)d_in[0];
    const float* cls   = (const float*)d_in[1];
    const float4* boxp = (const float4*)d_in[2];
    float* out = (float*)d_out;
    int M = in_sizes[0];
    if (M > MAXM) M = MAXM;
    (void)n_in;

    int gsc = (M + 511) / 512;
    int n4 = M >> 2;
    int gb = (n4 + 1023) / 1024;
    if (gb > 148) gb = 148;
    if (gb < 1) gb = 1;

    k_score<<<gsc, 512>>>(obj, cls, M);
    k_hist2<<<gb, 1024>>>(M);
    k_gather<<<gb, 1024>>>(M);
    k_rank<<<CAND_CAP / 32, 1024>>>(cls, boxp);
    k_sup<<<(TOPK + 31) / 32, 1024>>>();
    k_nms<<<1, 1024>>>(out, out_size);
}

// round 17
// speedup vs baseline: 1.3446x; 1.0499x over previous
#include <cuda_runtime.h>
#include <stdint.h>

// ---------------- problem constants ----------------
#define MAXM      300000
#define NCLS      80
#define TOPK      1000
#define CONF      0.001f
#define NMSTH     0.5f
#define CLSOFF    4096.0f
#define CAND_CAP  4096
#define NBINS     4096
#define NLCAP     384      // contested rows staged in static smem

// ---------------- device scratch (zero-initialized at load) ----------------
// All reset to zero at the END of k_nms for the next replay.
__device__ uint32_t g_scorebits[MAXM];
__device__ uint32_t g_hist1[NBINS];
__device__ uint32_t g_hist2[NBINS];
__device__ uint32_t g_prefix1;        // benign identical-value race (hist2 blocks)
__device__ uint32_t g_need;           // benign identical-value race (hist2 blocks)
__device__ uint32_t g_cand_cnt;
__device__ unsigned long long g_cand[CAND_CAP];
// ranked top-k data (fully overwritten each replay)
__device__ float   g_x1[TOPK], g_y1[TOPK], g_x2[TOPK], g_y2[TOPK];
__device__ float   g_area[TOPK], g_scr[TOPK];
__device__ float4  g_box[TOPK];
__device__ int     g_lab[TOPK];
__device__ uint32_t g_sup[TOPK * 32];  // fully overwritten each replay
__device__ uint32_t g_rowNZ[32];
__device__ uint32_t g_keep0[32];

__device__ __forceinline__ float sigf(float x) {
    return 1.0f / (1.0f + expf(-x));
}

// Two-level suffix scan (1024 threads): returns count strictly ABOVE this
// thread's chunk. warpTot = 32-entry smem array. Exactly 2 barriers.
__device__ __forceinline__ uint32_t suffix_above(uint32_t csum,
                                                 uint32_t* warpTot) {
    int lane = threadIdx.x & 31, warp = threadIdx.x >> 5;
    uint32_t S = csum;
#pragma unroll
    for (int off = 1; off < 32; off <<= 1) {
        uint32_t v = __shfl_down_sync(0xFFFFFFFFu, S, off);
        if (lane + off < 32) S += v;
    }
    if (lane == 0) warpTot[warp] = S;
    __syncthreads();
    if (threadIdx.x < 32) {
        uint32_t T = warpTot[threadIdx.x];
        uint32_t W = T;
#pragma unroll
        for (int off = 1; off < 32; off <<= 1) {
            uint32_t v = __shfl_down_sync(0xFFFFFFFFu, W, off);
            if (threadIdx.x + off < 32) W += v;
        }
        warpTot[threadIdx.x] = W - T;
    }
    __syncthreads();
    return warpTot[warp] + (S - csum);
}

// ============================================================================
// K1: coalesced max-logit (4 lanes/anchor, 5 even float4 loads/lane)
//     512 threads, 1024 anchors per block; fused score + 12-bit hist
// ============================================================================
__global__ void __launch_bounds__(512) k_score(const float* __restrict__ obj,
                                               const float* __restrict__ cls,
                                               int M) {
    __shared__ uint32_t sh[NBINS];
    for (int i = threadIdx.x; i < NBINS; i += 512) sh[i] = 0;
    __syncthreads();

    int warp = threadIdx.x >> 5, lane = threadIdx.x & 31;
    int g = lane >> 2, s = lane & 3;             // 8 anchors/warp/iter, 4 lanes each
    int base = blockIdx.x * 1024 + warp * 64;    // 16 warps x 64 anchors
    const float4* c4 = (const float4*)cls;

#pragma unroll
    for (int it = 0; it < 8; it++) {
        int m = base + it * 8 + g;
        float v = -1e30f;
        if (m < M) {
            const float4* row = c4 + (size_t)m * 20;
            float4 a0 = row[s];                 // 5 independent coalesced LDG.128
            float4 a1 = row[s + 4];
            float4 a2 = row[s + 8];
            float4 a3 = row[s + 12];
            float4 a4 = row[s + 16];
            float v0 = fmaxf(fmaxf(a0.x, a0.y), fmaxf(a0.z, a0.w));
            float v1 = fmaxf(fmaxf(a1.x, a1.y), fmaxf(a1.z, a1.w));
            float v2 = fmaxf(fmaxf(a2.x, a2.y), fmaxf(a2.z, a2.w));
            float v3 = fmaxf(fmaxf(a3.x, a3.y), fmaxf(a3.z, a3.w));
            float v4 = fmaxf(fmaxf(a4.x, a4.y), fmaxf(a4.z, a4.w));
            v = fmaxf(fmaxf(v0, v1), fmaxf(fmaxf(v2, v3), v4));
        }
        v = fmaxf(v, __shfl_down_sync(0xFFFFFFFFu, v, 2, 4));
        v = fmaxf(v, __shfl_down_sync(0xFFFFFFFFu, v, 1, 4));
        if (s == 0 && m < M) {
            // monotone: max_c sqrt(sig(o)*sig(c)) == sqrt(sig(o)*sig(max_c))
            float f = sqrtf(sigf(obj[m]) * sigf(v));
            uint32_t bits = __float_as_uint(f);
            g_scorebits[m] = bits;
            atomicAdd(&sh[bits >> 20], 1u);
        }
    }
    __syncthreads();
    for (int i = threadIdx.x; i < NBINS; i += 512) {
        uint32_t v = sh[i];
        if (v) atomicAdd(&g_hist1[i], v);
    }
}

// ============================================================================
// K2: INLINE redundant round-1 select (every block) + refinement hist
// ============================================================================
__global__ void __launch_bounds__(1024) k_hist2(int M) {
    __shared__ uint32_t sh[NBINS];
    __shared__ uint32_t warpTot[32];
    __shared__ uint32_t spre;
    int t = threadIdx.x;

    uint4 a = __ldcg(&((const uint4*)g_hist1)[t]);
    uint32_t hh[4] = {a.x, a.y, a.z, a.w};
    uint32_t csum = hh[0] + hh[1] + hh[2] + hh[3];
    uint32_t cum = suffix_above(csum, warpTot);
#pragma unroll
    for (int c = 3; c >= 0; c--) {
        uint32_t bc = hh[c];
        if (bc > 0 && cum < (uint32_t)TOPK && cum + bc >= (uint32_t)TOPK) {
            uint32_t pre = (uint32_t)(t * 4 + c) << 20;
            spre = pre;
            g_prefix1 = pre;              // identical across blocks: benign race
            g_need = (uint32_t)TOPK - cum;
        }
        cum += bc;
    }
    sh[t] = 0; sh[t + 1024] = 0; sh[t + 2048] = 0; sh[t + 3072] = 0;
    __syncthreads();
    uint32_t pre = spre;

    const uint4* sb4 = (const uint4*)g_scorebits;
    int n4 = M >> 2;
    for (int i = blockIdx.x * 1024 + t; i < n4; i += gridDim.x * 1024) {
        uint4 v = sb4[i];
        if ((v.x & 0xFFF00000u) == pre) atomicAdd(&sh[(v.x >> 8) & 0xFFFu], 1u);
        if ((v.y & 0xFFF00000u) == pre) atomicAdd(&sh[(v.y >> 8) & 0xFFFu], 1u);
        if ((v.z & 0xFFF00000u) == pre) atomicAdd(&sh[(v.z >> 8) & 0xFFFu], 1u);
        if ((v.w & 0xFFF00000u) == pre) atomicAdd(&sh[(v.w >> 8) & 0xFFFu], 1u);
    }
    if (blockIdx.x == 0 && t < (M & 3)) {
        uint32_t b = g_scorebits[(n4 << 2) + t];
        if ((b & 0xFFF00000u) == pre) atomicAdd(&sh[(b >> 8) & 0xFFFu], 1u);
    }
    __syncthreads();
    for (int i = t; i < NBINS; i += 1024) {
        uint32_t v = sh[i];
        if (v) atomicAdd(&g_hist2[i], v);
    }
}

// ============================================================================
// K3: INLINE redundant round-2 select (every block) + gather
// ============================================================================
__global__ void __launch_bounds__(1024) k_gather(int M) {
    __shared__ uint32_t warpTot[32];
    __shared__ uint32_t sT;
    int t = threadIdx.x;

    uint32_t need = g_need;
    uint32_t pre1 = g_prefix1;
    uint4 a = __ldcg(&((const uint4*)g_hist2)[t]);
    uint32_t hh[4] = {a.x, a.y, a.z, a.w};
    uint32_t csum = hh[0] + hh[1] + hh[2] + hh[3];
    uint32_t cum = suffix_above(csum, warpTot);
#pragma unroll
    for (int c = 3; c >= 0; c--) {
        uint32_t bc = hh[c];
        if (bc > 0 && cum < need && cum + bc >= need)
            sT = pre1 | ((uint32_t)(t * 4 + c) << 8);   // final 24-bit threshold
        cum += bc;
    }
    __syncthreads();
    uint32_t T = sT;

    const uint4* sb4 = (const uint4*)g_scorebits;
    int n4 = M >> 2;
    for (int i = blockIdx.x * 1024 + t; i < n4; i += gridDim.x * 1024) {
        uint4 v = sb4[i];
        uint32_t m0 = (uint32_t)(i << 2);
        uint32_t bb[4] = {v.x, v.y, v.z, v.w};
#pragma unroll
        for (int c = 0; c < 4; c++) {
            if (bb[c] >= T) {
                uint32_t p = atomicAdd(&g_cand_cnt, 1u);
                if (p < CAND_CAP)
                    g_cand[p] = ((unsigned long long)bb[c] << 32) |
                                (unsigned long long)(0xFFFFFFFFu - (m0 + c));
            }
        }
    }
    if (blockIdx.x == 0 && t < (M & 3)) {
        uint32_t m = (uint32_t)((n4 << 2) + t);
        uint32_t b = g_scorebits[m];
        if (b >= T) {
            uint32_t p = atomicAdd(&g_cand_cnt, 1u);
            if (p < CAND_CAP)
                g_cand[p] = ((unsigned long long)b << 32) |
                            (unsigned long long)(0xFFFFFFFFu - m);
        }
    }
}

// ============================================================================
// K4: warp-per-candidate rank (ballot count) + warp-parallel argmax + fetch
// ============================================================================
__global__ void __launch_bounds__(1024) k_rank(const float* __restrict__ cls,
                                               const float4* __restrict__ boxp) {
    __shared__ unsigned long long keys[CAND_CAP];
    int t = threadIdx.x;
    uint32_t n = g_cand_cnt;
    if (n > CAND_CAP) n = CAND_CAP;
    if ((uint32_t)(blockIdx.x * 32) >= n) return;   // block-uniform early exit

    for (uint32_t i = t; i < n; i += 1024) keys[i] = g_cand[i];
    __syncthreads();

    int warp = t >> 5, lane = t & 31;
    uint32_t c = blockIdx.x * 32 + warp;
    if (c >= n) return;                              // warp-uniform
    unsigned long long k = keys[c];

    int r = 0;
    for (uint32_t j0 = 0; j0 < n; j0 += 32) {
        uint32_t j = j0 + lane;
        bool p = (j < n) && (keys[j] > k);
        r += __popc(__ballot_sync(0xFFFFFFFFu, p));
    }
    if (r >= TOPK) return;

    uint32_t idx = 0xFFFFFFFFu - (uint32_t)(k & 0xFFFFFFFFull);

    // warp-parallel first-max argmax over 80 classes (20 lanes x 1 float4)
    float best = -1e30f;
    int lab = 0x7FFFFFFF;
    if (lane < 20) {
        float4 v = __ldg(&((const float4*)(cls + (size_t)idx * NCLS))[lane]);
        best = v.x; lab = lane * 4;
        if (v.y > best) { best = v.y; lab = lane * 4 + 1; }
        if (v.z > best) { best = v.z; lab = lane * 4 + 2; }
        if (v.w > best) { best = v.w; lab = lane * 4 + 3; }
    }
#pragma unroll
    for (int off = 16; off > 0; off >>= 1) {
        float ob = __shfl_down_sync(0xFFFFFFFFu, best, off);
        int   ol = __shfl_down_sync(0xFFFFFFFFu, lab, off);
        if (ob > best || (ob == best && ol < lab)) { best = ob; lab = ol; }
    }
    lab = __shfl_sync(0xFFFFFFFFu, lab, 0);          // first-max index

    if (lane == 0) {
        float scr = __uint_as_float((uint32_t)(k >> 32));
        float4 b = __ldg(&boxp[idx]);
        float off = (float)lab * CLSOFF;
        float x1 = b.x + off, y1 = b.y + off;
        float x2 = b.z + off, y2 = b.w + off;
        g_box[r] = b;
        g_scr[r] = scr;
        g_lab[r] = lab;
        g_x1[r] = x1; g_y1[r] = y1; g_x2[r] = x2; g_y2[r] = y2;
        g_area[r] = fmaxf(x2 - x1, 0.0f) * fmaxf(y2 - y1, 0.0f);
        if (scr > CONF) atomicOr(&g_keep0[r >> 5], 1u << (r & 31));
    }
}

// ============================================================================
// K5: suppression bit-matrix, grid-wide (32 blocks x 1024), boxes in smem
// ============================================================================
__global__ void k_sup() {
    __shared__ float sx1[TOPK], sy1[TOPK], sx2[TOPK], sy2[TOPK], sarea[TOPK];
    __shared__ int   slab[TOPK];
    int t = threadIdx.x;
    for (int i = t; i < TOPK; i += 1024) {
        sx1[i] = g_x1[i]; sy1[i] = g_y1[i];
        sx2[i] = g_x2[i]; sy2[i] = g_y2[i];
        sarea[i] = g_area[i]; slab[i] = g_lab[i];
    }
    __syncthreads();

    int w = t >> 5;          // j-word
    int lane = t & 31;       // row within this block's 32-row band
    int i = blockIdx.x * 32 + lane;
    int jbase = w * 32;
    uint32_t bits = 0;
    if (i < TOPK && jbase < i) {
        int lb = slab[i];
        float ix1 = sx1[i], iy1 = sy1[i], ix2 = sx2[i], iy2 = sy2[i];
        float ia = sarea[i];
        int jend = jbase + 32; if (jend > i) jend = i;
        for (int j = jbase; j < jend; j++) {
            if (slab[j] == lb) {   // cross-class IoU is exactly 0 (offset geometry)
                float xx1 = fmaxf(ix1, sx1[j]);
                float yy1 = fmaxf(iy1, sy1[j]);
                float xx2 = fminf(ix2, sx2[j]);
                float yy2 = fminf(iy2, sy2[j]);
                float inter = fmaxf(xx2 - xx1, 0.0f) * fmaxf(yy2 - yy1, 0.0f);
                float iou = inter / (ia + sarea[j] - inter + 1e-9f);
                if (iou > NMSTH) bits |= (1u << (j - jbase));
            }
        }
    }
    if (i < TOPK) {
        g_sup[i * 32 + w] = bits;
        if (bits) atomicOr(&g_rowNZ[i >> 5], 1u << (i & 31));
    }
}

// ============================================================================
// K6: sparse greedy sweep + output + state reset for next replay
// ============================================================================
__global__ void k_nms(float* __restrict__ out, int out_size) {
    __shared__ uint32_t srow[NLCAP * 32];   // 48 KB: staged contested rows
    __shared__ int      list[1024];
    __shared__ int      nlist;
    __shared__ uint32_t keep[32];
    __shared__ uint32_t rnz[32];

    int t = threadIdx.x;
    int lane = t & 31;
    if (t < 32) { keep[t] = g_keep0[t]; rnz[t] = g_rowNZ[t]; }
    __syncthreads();

    // warp 0: build ascending list of contested rows
    if (t < 32) {
        int cnt = 0;
        for (int w2 = 0; w2 < 32; w2++) {
            uint32_t rb = rnz[w2];
            int bit = (rb >> lane) & 1;
            uint32_t bal = __ballot_sync(0xFFFFFFFFu, bit);
            if (bit) {
                int pos = cnt + __popc(bal & ((1u << lane) - 1u));
                list[pos] = w2 * 32 + lane;
            }
            cnt += __popc(bal);
        }
        if (lane == 0) nlist = cnt;
    }
    __syncthreads();

    // stage contested rows (first NLCAP) into smem
    int nl = nlist;
    for (int l = t >> 5; l < nl && l < NLCAP; l += 32)
        srow[l * 32 + lane] = g_sup[list[l] * 32 + lane];
    __syncthreads();

    // warp 0: serial greedy sweep, lane owns keep-word lane
    if (t < 32) {
        uint32_t kw = keep[lane];
        for (int l = 0; l < nl; l++) {
            int i = list[l];
            int iw = i >> 5;
            uint32_t ib = (uint32_t)(i & 31);
            uint32_t ltm = (lane < iw) ? 0xFFFFFFFFu
                         : ((lane == iw) ? ((1u << ib) - 1u) : 0u);
            uint32_t row = (l < NLCAP) ? srow[l * 32 + lane]
                                       : g_sup[i * 32 + lane];
            uint32_t v = row & kw & ltm;
            if (__any_sync(0xFFFFFFFFu, v != 0u)) {
                if (lane == iw) kw &= ~(1u << ib);
            }
        }
        keep[lane] = kw;
    }
    __syncthreads();

    if (t < TOPK) {
        float kf = ((keep[t >> 5] >> (t & 31)) & 1u) ? 1.0f : 0.0f;
        float4 b = g_box[t];   // raw (un-offset) box, matches reference
        out[t * 5 + 0] = g_scr[t] * kf;
        out[t * 5 + 1] = b.x * kf;
        out[t * 5 + 2] = b.y * kf;
        out[t * 5 + 3] = b.z * kf;
        out[t * 5 + 4] = b.w * kf;
        if (out_size >= 6000) out[5000 + t] = (float)g_lab[t];
        if (out_size >= 7000) out[6000 + t] = kf;
    }

    // ---- reset all scratch state for the next replay ----
    for (int i = t; i < NBINS; i += 1024) { g_hist1[i] = 0; g_hist2[i] = 0; }
    if (t < 32) { g_rowNZ[t] = 0; g_keep0[t] = 0; }
    if (t == 0) g_cand_cnt = 0;
}

// ---------------- launch (6 kernels) ----------------
extern "C" void kernel_launch(void* const* d_in, const int* in_sizes, int n_in,
                              void* d_out, int out_size) {
    const float* obj   = (const float*)d_in[0];
    const float* cls   = (const float*)d_in[1];
    const float4* boxp = (const float4*)d_in[2];
    float* out = (float*)d_out;
    int M = in_sizes[0];
    if (M > MAXM) M = MAXM;
    (void)n_in;

    int gsc = (M + 1023) / 1024;
    int n4 = M >> 2;
    int gb = (n4 + 1023) / 1024;
    if (gb > 148) gb = 148;
    if (gb < 1) gb = 1;

    k_score<<<gsc, 512>>>(obj, cls, M);
    k_hist2<<<gb, 1024>>>(M);
    k_gather<<<gb, 1024>>>(M);
    k_rank<<<CAND_CAP / 32, 1024>>>(cls, boxp);
    k_sup<<<(TOPK + 31) / 32, 1024>>>();
    k_nms<<<1, 1024>>>(out, out_size);
}